// round 4
// baseline (speedup 1.0000x reference)
#include <cuda_runtime.h>
#include <math.h>

// ---------------- problem constants ----------------
#define MB      512
#define NN      100
#define TT      100
#define LL      50
#define HE      64
#define EE      128
#define NE      512
#define HD      256
#define MTOT    (MB*NN)     // 51200
#define BETA    0.25f

#define XH_ELEMS   (MTOT*TT)        // 5,120,000
#define OFF_RECON  (XH_ELEMS)
#define OFF_VQ     (XH_ELEMS+1)
#define OFF_IDX    (XH_ELEMS+2)

// ---------------- device scratch (modest: ~26.5MB total) ----------------
__device__ float g_z[MTOT*EE];
__device__ int   g_idx[MTOT];
__device__ float g_cnorm[NE];
__device__ float g_acc[4];          // recon_num, recon_den, vq_num, mask_sum
__device__ int   g_afirst_is_x;

// ---------------- zero the whole output (canary + required init) --------
__global__ void k_zero(float* __restrict__ outp, int n) {
    int i = blockIdx.x*256 + threadIdx.x;
    int stride = gridDim.x*256;
    for (; i < n; i += stride) outp[i] = 0.f;
}

// ---------------- init: acc, codebook norms, x/mask flag ----------------
__global__ void k_init(const float* __restrict__ cb, const float* __restrict__ candA) {
    int j = blockIdx.x*256 + threadIdx.x;
    if (j < 4) g_acc[j] = 0.f;
    if (j == 4) {
        int all01 = 1;
        if (candA) {
            for (int i = 0; i < 256; i++) {
                float v = candA[i];
                if (v != 0.f && v != 1.f) { all01 = 0; break; }
            }
        } else all01 = 0;
        g_afirst_is_x = all01 ? 0 : 1;
    }
    if (j < NE) {
        const float* c = cb + j*EE;
        float s = 0.f;
        for (int e = 0; e < EE; e++) { float v = c[e]; s += v*v; }
        g_cnorm[j] = s;
    }
}

// ---------------- encoder: 2 instances/block, 256 threads ---------------
__global__ __launch_bounds__(256)
void k_encode(const float* __restrict__ candA, const float* __restrict__ candB,
              const float* __restrict__ imask,
              const float* __restrict__ w1g, const float* __restrict__ b1g,
              const float* __restrict__ w2g, const float* __restrict__ b2g,
              const float* __restrict__ latw, const float* __restrict__ latb)
{
    __shared__ float s_h1[2*64*53];     // padded halo: p[0]=p[51]=0
    __shared__ float s_h0[2*2*52];
    __shared__ float s_w1[384];
    __shared__ float s_b1[64], s_b2[64];
    __shared__ float s_part[2*64*2];
    __shared__ float s_hbar[2*64];
    __shared__ float s_im[2];

    const int tid = threadIdx.x;
    const int m0  = blockIdx.x * 2;

    for (int i = tid; i < 2*64*53; i += 256) s_h1[i] = 0.f;
    for (int i = tid; i < 2*2*52;  i += 256) s_h0[i] = 0.f;
    for (int i = tid; i < 384;     i += 256) s_w1[i] = w1g[i];   // FIXED: was `if (tid<384)` with 256 threads
    if (tid < 64)  { s_b1[tid] = b1g[tid]; s_b2[tid] = b2g[tid]; }
    if (tid < 2)   s_im[tid] = imask[m0 + tid];
    __syncthreads();

    // masked input -> padded (inst, ch, l)
    for (int i = tid; i < 2*TT; i += 256) {
        int inst = i / TT, t = i % TT;
        int m = m0 + inst;
        float v = candA[(size_t)m*TT + t] * candB[(size_t)m*TT + t] * s_im[inst];
        s_h0[(inst*2 + (t & 1))*52 + 1 + (t >> 1)] = v;
    }
    __syncthreads();

    const int inst  = tid >> 7;       // 0..1
    const int t2    = tid & 127;
    const int o     = t2 >> 1;        // 0..63
    const int half  = t2 & 1;
    const int lbase = half * 25;

    // conv1: out h1[o][l] for 25 l's
    {
        float w[6];
        #pragma unroll
        for (int q = 0; q < 6; q++) w[q] = s_w1[o*6 + q];
        float bb = s_b1[o];
        const float* p0 = s_h0 + (inst*2 + 0)*52;
        const float* p1 = s_h0 + (inst*2 + 1)*52;
        float* dst = s_h1 + (inst*64 + o)*53;
        #pragma unroll 5
        for (int l = 0; l < 25; l++) {
            int li = lbase + l;
            float v = bb + w[0]*p0[li] + w[1]*p0[li+1] + w[2]*p0[li+2]
                         + w[3]*p1[li] + w[4]*p1[li+1] + w[5]*p1[li+2];
            dst[1 + li] = fmaxf(v, 0.f);
        }
    }
    __syncthreads();

    // conv2: acc[25] per (o, half); w2 streamed from global (L1/L2-hot)
    {
        float acc[25];
        float bb = s_b2[o];
        #pragma unroll
        for (int l = 0; l < 25; l++) acc[l] = bb;
        const float* h1b = s_h1 + (inst*64)*53;
        for (int i = 0; i < 64; i++) {
            float w0  = __ldg(w2g + (o*64 + i)*3 + 0);
            float w1v = __ldg(w2g + (o*64 + i)*3 + 1);
            float w2v = __ldg(w2g + (o*64 + i)*3 + 2);
            const float* p = h1b + i*53 + lbase;
            float a = p[0], b = p[1];
            #pragma unroll 5
            for (int l = 0; l < 25; l++) {
                float c = p[l + 2];
                acc[l] += w0*a + w1v*b + w2v*c;
                a = b; b = c;
            }
        }
        float s = 0.f;
        #pragma unroll
        for (int l = 0; l < 25; l++) s += fmaxf(acc[l], 0.f);
        s_part[(inst*64 + o)*2 + half] = s;
    }
    __syncthreads();

    if (t2 < 64)
        s_hbar[inst*64 + t2] = (s_part[(inst*64 + t2)*2] + s_part[(inst*64 + t2)*2 + 1]) * (1.f/50.f);
    __syncthreads();

    // latent: 128 outputs per instance
    {
        int e = t2;
        float acc = __ldg(latb + e);
        const float* hb = s_hbar + inst*64;
        #pragma unroll 8
        for (int i = 0; i < 64; i++) acc += __ldg(latw + e*64 + i) * hb[i];
        g_z[(size_t)(m0 + inst)*EE + e] = acc * s_im[inst];
    }
}

// ---------------- VQ: 32 instances/block, static smem ~35KB -------------
__device__ __forceinline__ unsigned fkey(float f) {
    unsigned u = __float_as_uint(f);
    return (u & 0x80000000u) ? ~u : (u | 0x80000000u);
}

__global__ __launch_bounds__(256)
void k_vq(const float* __restrict__ cb, const float* __restrict__ imask,
          float* __restrict__ outp, int out_size)
{
    __shared__ float s_z[32*128];               // 16 KB
    __shared__ float s_c[32*129];               // 16.5 KB
    __shared__ float s_cn[32];
    __shared__ float s_zn[32];
    __shared__ float s_imv[32];
    __shared__ unsigned long long s_best[32];

    const int tid = threadIdx.x;
    const int m0  = blockIdx.x * 32;

    for (int i = tid; i < 32*128; i += 256) s_z[i] = g_z[(size_t)m0*128 + i];
    if (tid < 32) { s_best[tid] = 0xFFFFFFFFFFFFFFFFull; s_imv[tid] = imask[m0 + tid]; }
    __syncthreads();
    if (tid < 32) {
        const float* z = s_z + tid*128;
        float s = 0.f;
        for (int e = 0; e < 128; e++) s += z[e]*z[e];
        s_zn[tid] = s;
    }

    const int ci  = tid & 31;
    const int grp = tid >> 5;       // 0..7 -> 4 instances each

    for (int tile = 0; tile < 16; tile++) {
        __syncthreads();
        for (int i = tid; i < 32*128; i += 256) {
            int row = i >> 7, e = i & 127;
            s_c[row*129 + e] = cb[(size_t)(tile*32 + row)*128 + e];
        }
        if (tid < 32) s_cn[tid] = g_cnorm[tile*32 + tid];
        __syncthreads();

        float dot[4] = {0.f, 0.f, 0.f, 0.f};
        const float* cr = s_c + ci*129;
        for (int e = 0; e < 128; e += 4) {
            float c0 = cr[e], c1 = cr[e+1], c2 = cr[e+2], c3 = cr[e+3];
            #pragma unroll
            for (int r = 0; r < 4; r++) {
                const float4 zv = *(const float4*)&s_z[(grp*4 + r)*128 + e];
                dot[r] += zv.x*c0 + zv.y*c1 + zv.z*c2 + zv.w*c3;
            }
        }
        float cn = s_cn[ci];
        int j = tile*32 + ci;
        #pragma unroll
        for (int r = 0; r < 4; r++) {
            float d = (s_zn[grp*4 + r] - 2.f*dot[r]) + cn;   // mimic ref formula
            unsigned long long pk = ((unsigned long long)fkey(d) << 32) | (unsigned)j;
            atomicMin(&s_best[grp*4 + r], pk);
        }
    }
    __syncthreads();

    if (tid < 32) {
        int j = (int)(s_best[tid] & 0xFFFFFFFFu);
        g_idx[m0 + tid] = j;
        float imv = s_imv[tid];
        if (out_size >= OFF_IDX + MTOT)
            outp[OFF_IDX + m0 + tid] = (imv > 0.f) ? (float)j : -1.f;
        atomicAdd(&g_acc[3], imv);
    }

    // vq loss: (1+BETA) * mean((z - c)^2) * im
    if (tid < 128) {
        int is = tid >> 2, q = tid & 3;
        int j = (int)(s_best[is] & 0xFFFFFFFFu) & (NE - 1);
        const float* c = cb + (size_t)j*128;
        const float* z = s_z + is*128;
        float s = 0.f;
        for (int e = q*32; e < q*32 + 32; e++) { float d = z[e] - c[e]; s += d*d; }
        s += __shfl_down_sync(0xffffffffu, s, 2, 4);
        s += __shfl_down_sync(0xffffffffu, s, 1, 4);
        if (q == 0) atomicAdd(&g_acc[2], s * ((1.f + BETA)/128.f) * s_imv[is]);
    }
}

// ---------------- fused decoder: 16 instances/block ---------------------
#define AP 260
__global__ __launch_bounds__(256)
void k_dec(const float* __restrict__ cb, const float* __restrict__ imask,
           const float* __restrict__ d1w, const float* __restrict__ d1b,
           const float* __restrict__ d2w, const float* __restrict__ d2b,
           const float* __restrict__ d3w, const float* __restrict__ d3b,
           const float* __restrict__ candA, const float* __restrict__ candB,
           float* __restrict__ outp)
{
    __shared__ float sA[16*AP];
    __shared__ float sB[16*AP];
    __shared__ float sW[8*AP];
    __shared__ float s_im[16];
    __shared__ int   s_j[16];

    const int tid = threadIdx.x;
    const int m0  = blockIdx.x * 16;

    if (tid < 16) { s_im[tid] = imask[m0 + tid]; s_j[tid] = g_idx[m0 + tid] & (NE - 1); }
    __syncthreads();

    // gather zq * im into sA[:, 0:128]
    for (int i = tid; i < 16*128; i += 256) {
        int ii = i >> 7, e = i & 127;
        sA[ii*AP + e] = cb[(size_t)s_j[ii]*128 + e] * s_im[ii];
    }
    __syncthreads();

    float acc[16];

    // ---- GEMM1: sB = relu(sA[:,0:128] @ d1w^T + d1b), Nout=256, K=128
    {
        #pragma unroll
        for (int ii = 0; ii < 16; ii++) acc[ii] = 0.f;
        for (int k0 = 0; k0 < 128; k0 += 8) {
            const int oo = tid >> 3, kk = tid & 7;
            #pragma unroll
            for (int p = 0; p < 8; p++)
                sW[kk*AP + oo + p*32] = __ldg(d1w + (size_t)(oo + p*32)*128 + k0 + kk);
            __syncthreads();
            float w[8];
            #pragma unroll
            for (int q = 0; q < 8; q++) w[q] = sW[q*AP + tid];
            #pragma unroll
            for (int ii = 0; ii < 16; ii++) {
                float4 a0 = *(const float4*)&sA[ii*AP + k0];
                float4 a1 = *(const float4*)&sA[ii*AP + k0 + 4];
                acc[ii] += w[0]*a0.x + w[1]*a0.y + w[2]*a0.z + w[3]*a0.w
                         + w[4]*a1.x + w[5]*a1.y + w[6]*a1.z + w[7]*a1.w;
            }
            __syncthreads();
        }
        float bb = __ldg(d1b + tid);
        #pragma unroll
        for (int ii = 0; ii < 16; ii++) sB[ii*AP + tid] = fmaxf(acc[ii] + bb, 0.f);
        __syncthreads();
    }

    // ---- GEMM2: sA = relu(sB @ d2w^T + d2b), Nout=256, K=256
    {
        #pragma unroll
        for (int ii = 0; ii < 16; ii++) acc[ii] = 0.f;
        for (int k0 = 0; k0 < 256; k0 += 8) {
            const int oo = tid >> 3, kk = tid & 7;
            #pragma unroll
            for (int p = 0; p < 8; p++)
                sW[kk*AP + oo + p*32] = __ldg(d2w + (size_t)(oo + p*32)*256 + k0 + kk);
            __syncthreads();
            float w[8];
            #pragma unroll
            for (int q = 0; q < 8; q++) w[q] = sW[q*AP + tid];
            #pragma unroll
            for (int ii = 0; ii < 16; ii++) {
                float4 a0 = *(const float4*)&sB[ii*AP + k0];
                float4 a1 = *(const float4*)&sB[ii*AP + k0 + 4];
                acc[ii] += w[0]*a0.x + w[1]*a0.y + w[2]*a0.z + w[3]*a0.w
                         + w[4]*a1.x + w[5]*a1.y + w[6]*a1.z + w[7]*a1.w;
            }
            __syncthreads();
        }
        float bb = __ldg(d2b + tid);
        #pragma unroll
        for (int ii = 0; ii < 16; ii++) sA[ii*AP + tid] = fmaxf(acc[ii] + bb, 0.f);
        __syncthreads();
    }

    // ---- GEMM3: x_hat = sA @ d3w^T + d3b, Nout=100, K=256 (+ recon loss)
    {
        #pragma unroll
        for (int ii = 0; ii < 16; ii++) acc[ii] = 0.f;
        for (int k0 = 0; k0 < 256; k0 += 8) {
            const int oo = tid >> 3, kk = tid & 7;
            #pragma unroll
            for (int p = 0; p < 4; p++) {
                int o = oo + p*32;
                if (o < 100) sW[kk*AP + o] = __ldg(d3w + (size_t)o*256 + k0 + kk);
            }
            __syncthreads();
            if (tid < 100) {
                float w[8];
                #pragma unroll
                for (int q = 0; q < 8; q++) w[q] = sW[q*AP + tid];
                #pragma unroll
                for (int ii = 0; ii < 16; ii++) {
                    float4 a0 = *(const float4*)&sA[ii*AP + k0];
                    float4 a1 = *(const float4*)&sA[ii*AP + k0 + 4];
                    acc[ii] += w[0]*a0.x + w[1]*a0.y + w[2]*a0.z + w[3]*a0.w
                             + w[4]*a1.x + w[5]*a1.y + w[6]*a1.z + w[7]*a1.w;
                }
            }
            __syncthreads();
        }

        const float* xr = candA; const float* tmr = candB;
        if (g_afirst_is_x == 0) { xr = candB; tmr = candA; }

        float rsum = 0.f, wsum = 0.f;
        if (tid < 100) {
            float bb = __ldg(d3b + tid);
            #pragma unroll
            for (int ii = 0; ii < 16; ii++) {
                int m = m0 + ii;
                float v = acc[ii] + bb;
                outp[(size_t)m*TT + tid] = v;
                float wgt = s_im[ii] * tmr[(size_t)m*TT + tid];
                float d = v - xr[(size_t)m*TT + tid];
                rsum += d*d*wgt; wsum += wgt;
            }
        }
        #pragma unroll
        for (int off = 16; off; off >>= 1) {
            rsum += __shfl_down_sync(0xffffffffu, rsum, off);
            wsum += __shfl_down_sync(0xffffffffu, wsum, off);
        }
        if ((tid & 31) == 0 && (rsum != 0.f || wsum != 0.f)) {
            atomicAdd(&g_acc[0], rsum);
            atomicAdd(&g_acc[1], wsum);
        }
    }
}

// ---------------- finalize ----------------------------------------------
__global__ void k_final(float* __restrict__ outp, int out_size) {
    if (out_size > OFF_VQ) {
        outp[OFF_RECON] = g_acc[0] / fmaxf(g_acc[1], 1.f);
        outp[OFF_VQ]    = g_acc[2] / fmaxf(g_acc[3], 1.f);
    }
}

// ---------------- launch -------------------------------------------------
extern "C" void kernel_launch(void* const* d_in, const int* in_sizes, int n_in,
                              void* d_out, int out_size)
{
    const float *candA=0,*candB=0,*im=0,*c1w=0,*c1b=0,*c2w=0,*c2b=0;
    const float *latw=0,*latb=0,*cb=0,*d1w=0,*d1b=0,*d2w=0,*d2b=0,*d3w=0,*d3b=0;

    // detect bytes-vs-elements
    int scale = 1;
    for (int i = 0; i < n_in; i++)
        if (in_sizes[i] == 5120000*4) { scale = 4; break; }

    int c5=0,c64=0,c256=0,c65k=0;
    for (int i = 0; i < n_in; i++) {
        const float* p = (const float*)d_in[i];
        int sz = in_sizes[i] / scale;
        switch (sz) {
            case 5120000: if (c5++ == 0) candA = p; else candB = p; break;
            case 51200:   im   = p; break;
            case 384:     c1w  = p; break;
            case 64:      if (c64++ == 0) c1b = p; else c2b = p; break;
            case 12288:   c2w  = p; break;
            case 8192:    latw = p; break;
            case 128:     latb = p; break;
            case 65536:   if (c65k++ == 0) cb = p; else d2w = p; break;
            case 32768:   d1w  = p; break;
            case 256:     if (c256++ == 0) d1b = p; else d2b = p; break;
            case 25600:   d3w  = p; break;
            case 100:     d3b  = p; break;
            default: break;
        }
    }
    // positional fallback (insertion order) if size matching failed
    if ((!candA || !candB || !im || !cb || !d1w || !d2w || !d3w) && n_in >= 16) {
        candA = (const float*)d_in[0];  candB = (const float*)d_in[1];
        im    = (const float*)d_in[2];
        c1w   = (const float*)d_in[3];  c1b   = (const float*)d_in[4];
        c2w   = (const float*)d_in[5];  c2b   = (const float*)d_in[6];
        latw  = (const float*)d_in[7];  latb  = (const float*)d_in[8];
        cb    = (const float*)d_in[9];
        d1w   = (const float*)d_in[10]; d1b   = (const float*)d_in[11];
        d2w   = (const float*)d_in[12]; d2b   = (const float*)d_in[13];
        d3w   = (const float*)d_in[14]; d3b   = (const float*)d_in[15];
    }
    if (!candB) candB = candA;

    float* outp = (float*)d_out;

    k_zero<<<2048, 256>>>(outp, out_size);
    k_init<<<2, 256>>>(cb, candA);
    k_encode<<<MTOT/2, 256>>>(candA, candB, im, c1w, c1b, c2w, c2b, latw, latb);
    k_vq<<<MTOT/32, 256>>>(cb, im, outp, out_size);
    k_dec<<<MTOT/16, 256>>>(cb, im, d1w, d1b, d2w, d2b, d3w, d3b, candA, candB, outp);
    k_final<<<1, 1>>>(outp, out_size);
}

// round 5
// speedup vs baseline: 2.4097x; 2.4097x over previous
#include <cuda_runtime.h>
#include <math.h>

// ---------------- problem constants ----------------
#define MB      512
#define NN      100
#define TT      100
#define LL      50
#define HE      64
#define EE      128
#define NE      512
#define HD      256
#define MTOT    (MB*NN)     // 51200
#define BETA    0.25f

#define XH_ELEMS   (MTOT*TT)        // 5,120,000
#define OFF_RECON  (XH_ELEMS)
#define OFF_VQ     (XH_ELEMS+1)
#define OFF_IDX    (XH_ELEMS+2)

typedef unsigned long long u64;

// ---- f32x2 helpers (sm_103a packed fp32) ----
__device__ __forceinline__ u64 pk2(float lo, float hi) {
    u64 r;
    asm("mov.b64 %0, {%1, %2};" : "=l"(r) : "r"(__float_as_uint(lo)), "r"(__float_as_uint(hi)));
    return r;
}
__device__ __forceinline__ void upk2(u64 v, float& lo, float& hi) {
    unsigned a, b;
    asm("mov.b64 {%0, %1}, %2;" : "=r"(a), "=r"(b) : "l"(v));
    lo = __uint_as_float(a); hi = __uint_as_float(b);
}
__device__ __forceinline__ u64 fma2(u64 a, u64 b, u64 c) {
    u64 d;
    asm("fma.rn.f32x2 %0, %1, %2, %3;" : "=l"(d) : "l"(a), "l"(b), "l"(c));
    return d;
}

// ---------------- device scratch ----------------
__device__ float g_z[MTOT*EE];
__device__ int   g_idx[MTOT];
__device__ float g_cnorm[NE];
__device__ float g_acc[4];          // recon_num, recon_den, vq_num, mask_sum
__device__ int   g_afirst_is_x;

// ---------------- zero output ----------------
__global__ void k_zero(float* __restrict__ outp, int n) {
    int i = blockIdx.x*256 + threadIdx.x;
    int stride = gridDim.x*256;
    for (; i < n; i += stride) outp[i] = 0.f;
}

// ---------------- init ----------------
__global__ void k_init(const float* __restrict__ cb, const float* __restrict__ candA) {
    int j = blockIdx.x*256 + threadIdx.x;
    if (j < 4) g_acc[j] = 0.f;
    if (j == 4) {
        int all01 = 1;
        if (candA) {
            for (int i = 0; i < 256; i++) {
                float v = candA[i];
                if (v != 0.f && v != 1.f) { all01 = 0; break; }
            }
        } else all01 = 0;
        g_afirst_is_x = all01 ? 0 : 1;
    }
    if (j < NE) {
        const float* c = cb + j*EE;
        float s = 0.f;
        for (int e = 0; e < EE; e++) { float v = c[e]; s += v*v; }
        g_cnorm[j] = s;
    }
}

// ---------------- encoder: 2 instances/block, 256 threads ---------------
// conv2 weights staged in smem by i-chunks; f32x2 pairs over l
__global__ __launch_bounds__(256)
void k_encode(const float* __restrict__ candA, const float* __restrict__ candB,
              const float* __restrict__ imask,
              const float* __restrict__ w1g, const float* __restrict__ b1g,
              const float* __restrict__ w2g, const float* __restrict__ b2g,
              const float* __restrict__ latw, const float* __restrict__ latb)
{
    __shared__ __align__(16) float s_h1[2*64*54];   // pitch 54 (even), halo pad
    __shared__ float s_w2c[64*49];                  // 16-i chunk of conv2 weights
    __shared__ float s_h0[2*2*52];
    __shared__ float s_w1[384];
    __shared__ float s_b1[64], s_b2[64];
    __shared__ float s_part[2*64*2];
    __shared__ float s_hbar[2*64];
    __shared__ float s_im[2];

    const int tid = threadIdx.x;
    const int m0  = blockIdx.x * 2;

    for (int i = tid; i < 2*64*54; i += 256) s_h1[i] = 0.f;
    for (int i = tid; i < 2*2*52;  i += 256) s_h0[i] = 0.f;
    for (int i = tid; i < 384;     i += 256) s_w1[i] = w1g[i];
    if (tid < 64)  { s_b1[tid] = b1g[tid]; s_b2[tid] = b2g[tid]; }
    if (tid < 2)   s_im[tid] = imask[m0 + tid];
    __syncthreads();

    // masked input -> padded (inst, ch, l)
    for (int i = tid; i < 2*TT; i += 256) {
        int inst = i / TT, t = i % TT;
        int m = m0 + inst;
        float v = candA[(size_t)m*TT + t] * candB[(size_t)m*TT + t] * s_im[inst];
        s_h0[(inst*2 + (t & 1))*52 + 1 + (t >> 1)] = v;
    }
    __syncthreads();

    const int inst  = tid >> 7;       // 0..1
    const int t2    = tid & 127;
    const int o     = t2 >> 1;        // 0..63
    const int half  = t2 & 1;

    // conv1 (2 -> 64, K=3, SAME) + relu; each thread 25 l's
    {
        const int lb1 = half * 25;
        float w[6];
        #pragma unroll
        for (int q = 0; q < 6; q++) w[q] = s_w1[o*6 + q];
        float bb = s_b1[o];
        const float* p0 = s_h0 + (inst*2 + 0)*52;
        const float* p1 = s_h0 + (inst*2 + 1)*52;
        float* dst = s_h1 + (inst*64 + o)*54;
        #pragma unroll 5
        for (int l = 0; l < 25; l++) {
            int li = lb1 + l;
            float v = bb + w[0]*p0[li] + w[1]*p0[li+1] + w[2]*p0[li+2]
                         + w[3]*p1[li] + w[4]*p1[li+1] + w[5]*p1[li+2];
            dst[1 + li] = fmaxf(v, 0.f);
        }
    }
    __syncthreads();

    // conv2 (64 -> 64, K=3, SAME) + relu + mean, f32x2, smem-staged weights
    {
        const int e0j   = half * 26;         // even start l (26/24 split)
        const int npair = 13 - half;         // 13 pairs (l 0..25) or 12 (l 26..49)
        u64 acc2[13];
        {
            float bb = s_b2[o];
            u64 bb2 = pk2(bb, bb);
            #pragma unroll
            for (int j = 0; j < 13; j++) acc2[j] = bb2;
        }
        const float* rowbase = s_h1 + (inst*64)*54 + e0j;
        for (int cb4 = 0; cb4 < 4; cb4++) {
            __syncthreads();
            for (int idx = tid; idx < 64*48; idx += 256) {
                int oo = idx / 48, r = idx - oo*48;
                s_w2c[oo*49 + r] = w2g[oo*192 + cb4*48 + r];
            }
            __syncthreads();
            for (int i2 = 0; i2 < 16; i2++) {
                const float* wr = s_w2c + o*49 + i2*3;
                u64 wp0 = pk2(wr[0], wr[0]);
                u64 wp1 = pk2(wr[1], wr[1]);
                u64 wp2 = pk2(wr[2], wr[2]);
                const float2* prow = (const float2*)(rowbase + (cb4*16 + i2)*54);
                float2 cur = prow[0];
                #pragma unroll
                for (int j = 0; j < 13; j++) {
                    float2 nxt = prow[j+1];
                    acc2[j] = fma2(wp0, pk2(cur.x, cur.y), acc2[j]);
                    acc2[j] = fma2(wp1, pk2(cur.y, nxt.x), acc2[j]);
                    acc2[j] = fma2(wp2, pk2(nxt.x, nxt.y), acc2[j]);
                    cur = nxt;
                }
            }
        }
        float s = 0.f;
        for (int j = 0; j < npair; j++) {
            float lo, hi; upk2(acc2[j], lo, hi);
            s += fmaxf(lo, 0.f) + fmaxf(hi, 0.f);
        }
        s_part[(inst*64 + o)*2 + half] = s;
    }
    __syncthreads();

    if (t2 < 64)
        s_hbar[inst*64 + t2] = (s_part[(inst*64 + t2)*2] + s_part[(inst*64 + t2)*2 + 1]) * (1.f/50.f);
    __syncthreads();

    // latent: 128 outputs per instance
    {
        int e = t2;
        float acc = __ldg(latb + e);
        const float* hb = s_hbar + inst*64;
        #pragma unroll 8
        for (int i = 0; i < 64; i++) acc += __ldg(latw + e*64 + i) * hb[i];
        g_z[(size_t)(m0 + inst)*EE + e] = acc * s_im[inst];
    }
}

// ---------------- VQ: 32 inst/block, 2 inst x 2 codes per thread, f32x2 --
__device__ __forceinline__ unsigned fkey(float f) {
    unsigned u = __float_as_uint(f);
    return (u & 0x80000000u) ? ~u : (u | 0x80000000u);
}

__global__ __launch_bounds__(256)
void k_vq(const float* __restrict__ cb, const float* __restrict__ imask,
          float* __restrict__ outp, int out_size)
{
    __shared__ __align__(16) float s_z[32*128];     // 16 KB
    __shared__ __align__(16) float s_c[32*130];     // 16.6 KB (even pitch)
    __shared__ float s_cn[32];
    __shared__ float s_zn[32];
    __shared__ float s_imv[32];
    __shared__ unsigned long long s_best[32];

    const int tid = threadIdx.x;
    const int m0  = blockIdx.x * 32;

    for (int i = tid; i < 32*128; i += 256) s_z[i] = g_z[(size_t)m0*128 + i];
    if (tid < 32) { s_best[tid] = 0xFFFFFFFFFFFFFFFFull; s_imv[tid] = imask[m0 + tid]; }
    __syncthreads();
    if (tid < 32) {
        const float* z = s_z + tid*128;
        float s = 0.f;
        for (int e = 0; e < 128; e++) s += z[e]*z[e];
        s_zn[tid] = s;
    }

    const int ci  = tid & 15;       // codes ci and ci+16 within 32-code tile
    const int grp = tid >> 4;       // instances grp*2, grp*2+1

    const u64* zpa = (const u64*)(s_z + (grp*2 + 0)*128);
    const u64* zpb = (const u64*)(s_z + (grp*2 + 1)*128);
    const u64* cpa = (const u64*)(s_c + ci*130);
    const u64* cpb = (const u64*)(s_c + (ci + 16)*130);

    for (int tile = 0; tile < 16; tile++) {
        __syncthreads();
        for (int i = tid; i < 32*128; i += 256) {
            int row = i >> 7, e = i & 127;
            s_c[row*130 + e] = cb[(size_t)(tile*32 + row)*128 + e];
        }
        if (tid < 32) s_cn[tid] = g_cnorm[tile*32 + tid];
        __syncthreads();

        u64 d00 = 0, d01 = 0, d10 = 0, d11 = 0;   // (inst a/b) x (code 0/1), packed pair-sums
        #pragma unroll 4
        for (int e2 = 0; e2 < 64; e2++) {
            u64 za = zpa[e2], zb = zpb[e2];
            u64 ca = cpa[e2], cbv = cpb[e2];
            d00 = fma2(za, ca,  d00);
            d01 = fma2(za, cbv, d01);
            d10 = fma2(zb, ca,  d10);
            d11 = fma2(zb, cbv, d11);
        }
        float lo, hi;
        float dot[2][2];
        upk2(d00, lo, hi); dot[0][0] = lo + hi;
        upk2(d01, lo, hi); dot[0][1] = lo + hi;
        upk2(d10, lo, hi); dot[1][0] = lo + hi;
        upk2(d11, lo, hi); dot[1][1] = lo + hi;

        #pragma unroll
        for (int cc = 0; cc < 2; cc++) {
            int code = ci + cc*16;
            float cn = s_cn[code];
            int j = tile*32 + code;
            #pragma unroll
            for (int r = 0; r < 2; r++) {
                float d = (s_zn[grp*2 + r] - 2.f*dot[r][cc]) + cn;
                unsigned long long pkv = ((unsigned long long)fkey(d) << 32) | (unsigned)j;
                atomicMin(&s_best[grp*2 + r], pkv);
            }
        }
    }
    __syncthreads();

    if (tid < 32) {
        int j = (int)(s_best[tid] & 0xFFFFFFFFu);
        g_idx[m0 + tid] = j;
        float imv = s_imv[tid];
        if (out_size >= OFF_IDX + MTOT)
            outp[OFF_IDX + m0 + tid] = (imv > 0.f) ? (float)j : -1.f;
        atomicAdd(&g_acc[3], imv);
    }

    // vq loss: (1+BETA) * mean((z - c)^2) * im
    if (tid < 128) {
        int is = tid >> 2, q = tid & 3;
        int j = (int)(s_best[is] & 0xFFFFFFFFu) & (NE - 1);
        const float* c = cb + (size_t)j*128;
        const float* z = s_z + is*128;
        float s = 0.f;
        for (int e = q*32; e < q*32 + 32; e++) { float d = z[e] - c[e]; s += d*d; }
        s += __shfl_down_sync(0xffffffffu, s, 2, 4);
        s += __shfl_down_sync(0xffffffffu, s, 1, 4);
        if (q == 0) atomicAdd(&g_acc[2], s * ((1.f + BETA)/128.f) * s_imv[is]);
    }
}

// ---------------- fused decoder: 16 instances/block, f32x2 --------------
#define AP 260
__global__ __launch_bounds__(256)
void k_dec(const float* __restrict__ cb, const float* __restrict__ imask,
           const float* __restrict__ d1w, const float* __restrict__ d1b,
           const float* __restrict__ d2w, const float* __restrict__ d2b,
           const float* __restrict__ d3w, const float* __restrict__ d3b,
           const float* __restrict__ candA, const float* __restrict__ candB,
           float* __restrict__ outp)
{
    __shared__ __align__(16) float sA[16*AP];
    __shared__ __align__(16) float sB[16*AP];
    __shared__ float sW[8*AP];
    __shared__ float s_im[16];
    __shared__ int   s_j[16];

    const int tid = threadIdx.x;
    const int m0  = blockIdx.x * 16;

    if (tid < 16) { s_im[tid] = imask[m0 + tid]; s_j[tid] = g_idx[m0 + tid] & (NE - 1); }
    __syncthreads();

    for (int i = tid; i < 16*128; i += 256) {
        int ii = i >> 7, e = i & 127;
        sA[ii*AP + e] = cb[(size_t)s_j[ii]*128 + e] * s_im[ii];
    }
    __syncthreads();

    u64 acc2[16];

    // ---- GEMM1: sB = relu(sA[:,0:128] @ d1w^T + d1b), Nout=256, K=128
    {
        #pragma unroll
        for (int ii = 0; ii < 16; ii++) acc2[ii] = 0;
        for (int k0 = 0; k0 < 128; k0 += 8) {
            const int oo = tid >> 3, kk = tid & 7;
            #pragma unroll
            for (int p = 0; p < 8; p++)
                sW[kk*AP + oo + p*32] = __ldg(d1w + (size_t)(oo + p*32)*128 + k0 + kk);
            __syncthreads();
            float w[8];
            #pragma unroll
            for (int q = 0; q < 8; q++) w[q] = sW[q*AP + tid];
            u64 wp0 = pk2(w[0], w[1]), wp1 = pk2(w[2], w[3]);
            u64 wp2 = pk2(w[4], w[5]), wp3 = pk2(w[6], w[7]);
            #pragma unroll
            for (int ii = 0; ii < 16; ii++) {
                const u64* ap = (const u64*)&sA[ii*AP + k0];
                acc2[ii] = fma2(wp0, ap[0], acc2[ii]);
                acc2[ii] = fma2(wp1, ap[1], acc2[ii]);
                acc2[ii] = fma2(wp2, ap[2], acc2[ii]);
                acc2[ii] = fma2(wp3, ap[3], acc2[ii]);
            }
            __syncthreads();
        }
        float bb = __ldg(d1b + tid);
        #pragma unroll
        for (int ii = 0; ii < 16; ii++) {
            float lo, hi; upk2(acc2[ii], lo, hi);
            sB[ii*AP + tid] = fmaxf(lo + hi + bb, 0.f);
        }
        __syncthreads();
    }

    // ---- GEMM2: sA = relu(sB @ d2w^T + d2b), Nout=256, K=256
    {
        #pragma unroll
        for (int ii = 0; ii < 16; ii++) acc2[ii] = 0;
        for (int k0 = 0; k0 < 256; k0 += 8) {
            const int oo = tid >> 3, kk = tid & 7;
            #pragma unroll
            for (int p = 0; p < 8; p++)
                sW[kk*AP + oo + p*32] = __ldg(d2w + (size_t)(oo + p*32)*256 + k0 + kk);
            __syncthreads();
            float w[8];
            #pragma unroll
            for (int q = 0; q < 8; q++) w[q] = sW[q*AP + tid];
            u64 wp0 = pk2(w[0], w[1]), wp1 = pk2(w[2], w[3]);
            u64 wp2 = pk2(w[4], w[5]), wp3 = pk2(w[6], w[7]);
            #pragma unroll
            for (int ii = 0; ii < 16; ii++) {
                const u64* ap = (const u64*)&sB[ii*AP + k0];
                acc2[ii] = fma2(wp0, ap[0], acc2[ii]);
                acc2[ii] = fma2(wp1, ap[1], acc2[ii]);
                acc2[ii] = fma2(wp2, ap[2], acc2[ii]);
                acc2[ii] = fma2(wp3, ap[3], acc2[ii]);
            }
            __syncthreads();
        }
        float bb = __ldg(d2b + tid);
        #pragma unroll
        for (int ii = 0; ii < 16; ii++) {
            float lo, hi; upk2(acc2[ii], lo, hi);
            sA[ii*AP + tid] = fmaxf(lo + hi + bb, 0.f);
        }
        __syncthreads();
    }

    // ---- GEMM3: x_hat = sA @ d3w^T + d3b, Nout=100, K=256 (+ recon)
    {
        #pragma unroll
        for (int ii = 0; ii < 16; ii++) acc2[ii] = 0;
        for (int k0 = 0; k0 < 256; k0 += 8) {
            const int oo = tid >> 3, kk = tid & 7;
            #pragma unroll
            for (int p = 0; p < 4; p++) {
                int ox = oo + p*32;
                if (ox < 100) sW[kk*AP + ox] = __ldg(d3w + (size_t)ox*256 + k0 + kk);
            }
            __syncthreads();
            if (tid < 100) {
                float w[8];
                #pragma unroll
                for (int q = 0; q < 8; q++) w[q] = sW[q*AP + tid];
                u64 wp0 = pk2(w[0], w[1]), wp1 = pk2(w[2], w[3]);
                u64 wp2 = pk2(w[4], w[5]), wp3 = pk2(w[6], w[7]);
                #pragma unroll
                for (int ii = 0; ii < 16; ii++) {
                    const u64* ap = (const u64*)&sA[ii*AP + k0];
                    acc2[ii] = fma2(wp0, ap[0], acc2[ii]);
                    acc2[ii] = fma2(wp1, ap[1], acc2[ii]);
                    acc2[ii] = fma2(wp2, ap[2], acc2[ii]);
                    acc2[ii] = fma2(wp3, ap[3], acc2[ii]);
                }
            }
            __syncthreads();
        }

        const float* xr = candA; const float* tmr = candB;
        if (g_afirst_is_x == 0) { xr = candB; tmr = candA; }

        float rsum = 0.f, wsum = 0.f;
        if (tid < 100) {
            float bb = __ldg(d3b + tid);
            #pragma unroll
            for (int ii = 0; ii < 16; ii++) {
                int m = m0 + ii;
                float lo, hi; upk2(acc2[ii], lo, hi);
                float v = lo + hi + bb;
                outp[(size_t)m*TT + tid] = v;
                float wgt = s_im[ii] * tmr[(size_t)m*TT + tid];
                float d = v - xr[(size_t)m*TT + tid];
                rsum += d*d*wgt; wsum += wgt;
            }
        }
        #pragma unroll
        for (int off = 16; off; off >>= 1) {
            rsum += __shfl_down_sync(0xffffffffu, rsum, off);
            wsum += __shfl_down_sync(0xffffffffu, wsum, off);
        }
        if ((tid & 31) == 0 && (rsum != 0.f || wsum != 0.f)) {
            atomicAdd(&g_acc[0], rsum);
            atomicAdd(&g_acc[1], wsum);
        }
    }
}

// ---------------- finalize ----------------
__global__ void k_final(float* __restrict__ outp, int out_size) {
    if (out_size > OFF_VQ) {
        outp[OFF_RECON] = g_acc[0] / fmaxf(g_acc[1], 1.f);
        outp[OFF_VQ]    = g_acc[2] / fmaxf(g_acc[3], 1.f);
    }
}

// ---------------- launch ----------------
extern "C" void kernel_launch(void* const* d_in, const int* in_sizes, int n_in,
                              void* d_out, int out_size)
{
    const float *candA=0,*candB=0,*im=0,*c1w=0,*c1b=0,*c2w=0,*c2b=0;
    const float *latw=0,*latb=0,*cb=0,*d1w=0,*d1b=0,*d2w=0,*d2b=0,*d3w=0,*d3b=0;

    int scale = 1;
    for (int i = 0; i < n_in; i++)
        if (in_sizes[i] == 5120000*4) { scale = 4; break; }

    int c5=0,c64=0,c256=0,c65k=0;
    for (int i = 0; i < n_in; i++) {
        const float* p = (const float*)d_in[i];
        int sz = in_sizes[i] / scale;
        switch (sz) {
            case 5120000: if (c5++ == 0) candA = p; else candB = p; break;
            case 51200:   im   = p; break;
            case 384:     c1w  = p; break;
            case 64:      if (c64++ == 0) c1b = p; else c2b = p; break;
            case 12288:   c2w  = p; break;
            case 8192:    latw = p; break;
            case 128:     latb = p; break;
            case 65536:   if (c65k++ == 0) cb = p; else d2w = p; break;
            case 32768:   d1w  = p; break;
            case 256:     if (c256++ == 0) d1b = p; else d2b = p; break;
            case 25600:   d3w  = p; break;
            case 100:     d3b  = p; break;
            default: break;
        }
    }
    if ((!candA || !candB || !im || !cb || !d1w || !d2w || !d3w) && n_in >= 16) {
        candA = (const float*)d_in[0];  candB = (const float*)d_in[1];
        im    = (const float*)d_in[2];
        c1w   = (const float*)d_in[3];  c1b   = (const float*)d_in[4];
        c2w   = (const float*)d_in[5];  c2b   = (const float*)d_in[6];
        latw  = (const float*)d_in[7];  latb  = (const float*)d_in[8];
        cb    = (const float*)d_in[9];
        d1w   = (const float*)d_in[10]; d1b   = (const float*)d_in[11];
        d2w   = (const float*)d_in[12]; d2b   = (const float*)d_in[13];
        d3w   = (const float*)d_in[14]; d3b   = (const float*)d_in[15];
    }
    if (!candB) candB = candA;

    float* outp = (float*)d_out;

    k_zero<<<2048, 256>>>(outp, out_size);
    k_init<<<2, 256>>>(cb, candA);
    k_encode<<<MTOT/2, 256>>>(candA, candB, im, c1w, c1b, c2w, c2b, latw, latb);
    k_vq<<<MTOT/32, 256>>>(cb, im, outp, out_size);
    k_dec<<<MTOT/16, 256>>>(cb, im, d1w, d1b, d2w, d2b, d3w, d3b, candA, candB, outp);
    k_final<<<1, 1>>>(outp, out_size);
}

// round 6
// speedup vs baseline: 2.4207x; 1.0046x over previous
#include <cuda_runtime.h>
#include <math.h>

// ---------------- problem constants ----------------
#define MB      512
#define NN      100
#define TT      100
#define LL      50
#define HE      64
#define EE      128
#define NE      512
#define HD      256
#define MTOT    (MB*NN)     // 51200
#define BETA    0.25f

#define XH_ELEMS   (MTOT*TT)        // 5,120,000
#define OFF_RECON  (XH_ELEMS)
#define OFF_VQ     (XH_ELEMS+1)
#define OFF_IDX    (XH_ELEMS+2)

typedef unsigned long long u64;

// ---- f32x2 helpers ----
__device__ __forceinline__ u64 pk2(float lo, float hi) {
    u64 r;
    asm("mov.b64 %0, {%1, %2};" : "=l"(r) : "r"(__float_as_uint(lo)), "r"(__float_as_uint(hi)));
    return r;
}
__device__ __forceinline__ void upk2(u64 v, float& lo, float& hi) {
    unsigned a, b;
    asm("mov.b64 {%0, %1}, %2;" : "=r"(a), "=r"(b) : "l"(v));
    lo = __uint_as_float(a); hi = __uint_as_float(b);
}
__device__ __forceinline__ u64 fma2(u64 a, u64 b, u64 c) {
    u64 d;
    asm("fma.rn.f32x2 %0, %1, %2, %3;" : "=l"(d) : "l"(a), "l"(b), "l"(c));
    return d;
}

// ---------------- device scratch ----------------
__device__ float g_z[MTOT*EE];
__device__ int   g_idx[MTOT];
__device__ float g_cnorm[NE];
__device__ float g_acc[4];          // recon_num, recon_den, vq_num, mask_sum
__device__ int   g_afirst_is_x;

// ---------------- zero tail of output ----------------
__global__ void k_zerotail(float* __restrict__ p, int n) {
    int i = blockIdx.x*256 + threadIdx.x;
    int stride = gridDim.x*256;
    for (; i < n; i += stride) p[i] = 0.f;
}

// ---------------- init ----------------
__global__ void k_init(const float* __restrict__ cb, const float* __restrict__ candA) {
    int j = blockIdx.x*256 + threadIdx.x;
    if (j < 4) g_acc[j] = 0.f;
    if (j == 4) {
        int all01 = 1;
        if (candA) {
            for (int i = 0; i < 256; i++) {
                float v = candA[i];
                if (v != 0.f && v != 1.f) { all01 = 0; break; }
            }
        } else all01 = 0;
        g_afirst_is_x = all01 ? 0 : 1;
    }
    if (j < NE) {
        const float* c = cb + j*EE;
        float s = 0.f;
        for (int e = 0; e < EE; e++) { float v = c[e]; s += v*v; }
        g_cnorm[j] = s;
    }
}

// ---------------- encoder: 2 inst/block, 128 threads ---------------
// conv2: channel-pair f32x2 packing (o, o+32), transposed smem weights.
__global__ __launch_bounds__(128)
void k_encode(const float* __restrict__ candA, const float* __restrict__ candB,
              const float* __restrict__ imask,
              const float* __restrict__ w1g, const float* __restrict__ b1g,
              const float* __restrict__ w2g, const float* __restrict__ b2g,
              const float* __restrict__ latw, const float* __restrict__ latb)
{
    __shared__ float s_h1[2*64*54];     // padded: [0]=0, data 1..50, [51..53]=0
    __shared__ float s_w2t[48*64];      // transposed chunk: [(i2*3+k)*64 + o]
    __shared__ float s_h0[2*2*52];
    __shared__ float s_w1[384];
    __shared__ float s_b1[64], s_b2[64];
    __shared__ __align__(16) float s_part[2*64*2];
    __shared__ __align__(16) float s_hbar[2*64];
    __shared__ float s_im[2];

    const int tid = threadIdx.x;
    const int m0  = blockIdx.x * 2;

    for (int i = tid; i < 2*64*54; i += 128) s_h1[i] = 0.f;
    for (int i = tid; i < 2*2*52;  i += 128) s_h0[i] = 0.f;
    for (int i = tid; i < 384;     i += 128) s_w1[i] = w1g[i];
    if (tid < 64)  { s_b1[tid] = b1g[tid]; s_b2[tid] = b2g[tid]; }
    if (tid < 2)   s_im[tid] = imask[m0 + tid];
    __syncthreads();

    // masked input -> padded (inst, ch, l)
    for (int i = tid; i < 2*TT; i += 128) {
        int inst = i / TT, t = i - (i/TT)*TT;
        int m = m0 + inst;
        float v = candA[(size_t)m*TT + t] * candB[(size_t)m*TT + t] * s_im[inst];
        s_h0[(inst*2 + (t & 1))*52 + 1 + (t >> 1)] = v;
    }
    __syncthreads();

    // conv1: one (inst, o) row per thread, all 50 l
    {
        const int inst = tid >> 6, o = tid & 63;
        float w[6];
        #pragma unroll
        for (int q = 0; q < 6; q++) w[q] = s_w1[o*6 + q];
        float bb = s_b1[o];
        const float* p0 = s_h0 + (inst*2 + 0)*52;
        const float* p1 = s_h0 + (inst*2 + 1)*52;
        float* dst = s_h1 + (inst*64 + o)*54;
        #pragma unroll 10
        for (int l = 0; l < LL; l++) {
            float v = bb + w[0]*p0[l] + w[1]*p0[l+1] + w[2]*p0[l+2]
                         + w[3]*p1[l] + w[4]*p1[l+1] + w[5]*p1[l+2];
            dst[1 + l] = fmaxf(v, 0.f);
        }
    }
    __syncthreads();

    // conv2: thread = (inst, half, o32); channels (o32, o32+32) packed; 25 l each
    {
        const int o32  = tid & 31;
        const int half = (tid >> 5) & 1;
        const int inst = tid >> 6;
        const int lb   = half * 25;

        u64 acc2[25];
        {
            u64 bb2 = pk2(s_b2[o32], s_b2[o32 + 32]);
            #pragma unroll
            for (int t = 0; t < 25; t++) acc2[t] = bb2;
        }

        for (int chunk = 0; chunk < 4; chunk++) {
            __syncthreads();
            for (int idx = tid; idx < 48*64; idx += 128) {
                int o = idx & 63, r = idx >> 6;                 // r in [0,48)
                s_w2t[r*64 + o] = w2g[o*192 + chunk*48 + r];
            }
            __syncthreads();
            #pragma unroll 2
            for (int i2 = 0; i2 < 16; i2++) {
                const float* wb = s_w2t + (i2*3)*64;
                u64 w0p = pk2(wb[o32],        wb[o32 + 32]);
                u64 w1p = pk2(wb[64 + o32],   wb[96 + o32]);
                u64 w2p = pk2(wb[128 + o32],  wb[160 + o32]);
                const float* hrow = s_h1 + (inst*64 + chunk*16 + i2)*54 + lb;
                #pragma unroll
                for (int x = 0; x < 27; x++) {
                    float h = hrow[x];
                    u64 s = pk2(h, h);
                    if (x <= 24)            acc2[x]   = fma2(w0p, s, acc2[x]);
                    if (x >= 1 && x <= 25)  acc2[x-1] = fma2(w1p, s, acc2[x-1]);
                    if (x >= 2)             acc2[x-2] = fma2(w2p, s, acc2[x-2]);
                }
            }
        }
        float slo = 0.f, shi = 0.f;
        #pragma unroll
        for (int t = 0; t < 25; t++) {
            float lo, hi; upk2(acc2[t], lo, hi);
            slo += fmaxf(lo, 0.f);
            shi += fmaxf(hi, 0.f);
        }
        s_part[(inst*64 + o32)*2 + half]        = slo;
        s_part[(inst*64 + o32 + 32)*2 + half]   = shi;
    }
    __syncthreads();

    {
        const int inst = tid >> 6, o = tid & 63;
        s_hbar[inst*64 + o] = (s_part[(inst*64 + o)*2] + s_part[(inst*64 + o)*2 + 1]) * (1.f/50.f);
    }
    __syncthreads();

    // latent: 2 outputs per thread, f32x2 over k-pairs
    {
        const int inst = tid >> 6, e0 = tid & 63;
        const u64* hb2 = (const u64*)(s_hbar + inst*64);
        #pragma unroll
        for (int ee = 0; ee < 2; ee++) {
            int e = e0 + 64*ee;
            const u64* lw = (const u64*)latw + e*32;
            u64 acc = 0;
            #pragma unroll 8
            for (int kk = 0; kk < 32; kk++) acc = fma2(__ldg(lw + kk), hb2[kk], acc);
            float lo, hi; upk2(acc, lo, hi);
            g_z[(size_t)(m0 + inst)*EE + e] = (lo + hi + __ldg(latb + e)) * s_im[inst];
        }
    }
}

// ---------------- VQ: 64 inst/block, 4z x 4c register tile ----------------
__device__ __forceinline__ unsigned fkey(float f) {
    unsigned u = __float_as_uint(f);
    return (u & 0x80000000u) ? ~u : (u | 0x80000000u);
}

__global__ __launch_bounds__(256)
void k_vq(const float* __restrict__ cb, const float* __restrict__ imask,
          float* __restrict__ outp, int out_size)
{
    __shared__ __align__(16) float s_z[64*128];     // 32 KB
    __shared__ __align__(16) float s_c[64*130];     // 33.3 KB
    __shared__ float s_cn[64], s_zn[64], s_imv[64];
    __shared__ u64   s_best[64];

    const int tid = threadIdx.x;
    const int m0  = blockIdx.x * 64;

    for (int i = tid; i < 64*128; i += 256) s_z[i] = g_z[(size_t)m0*128 + i];
    if (tid < 64) { s_best[tid] = 0xFFFFFFFFFFFFFFFFull; s_imv[tid] = imask[m0 + tid]; }
    __syncthreads();
    if (tid < 64) {
        const float* z = s_z + tid*128;
        float s = 0.f;
        for (int e = 0; e < 128; e++) s += z[e]*z[e];
        s_zn[tid] = s;
    }

    const int cq = tid & 15;        // c rows cq + 16q
    const int zq = tid >> 4;        // z rows zq + 16r

    float bd[4]; int bj[4];
    #pragma unroll
    for (int r = 0; r < 4; r++) { bd[r] = 3.4e38f; bj[r] = 0; }

    const u64* zp[4];
    #pragma unroll
    for (int r = 0; r < 4; r++) zp[r] = (const u64*)(s_z + (zq + 16*r)*128);

    for (int tile = 0; tile < 8; tile++) {
        __syncthreads();
        for (int i = tid; i < 64*128; i += 256) {
            int row = i >> 7, e = i & 127;
            s_c[row*130 + e] = cb[(size_t)(tile*64 + row)*128 + e];
        }
        if (tid < 64) s_cn[tid] = g_cnorm[tile*64 + tid];
        __syncthreads();

        u64 dt[4][4];
        #pragma unroll
        for (int r = 0; r < 4; r++)
            #pragma unroll
            for (int q = 0; q < 4; q++) dt[r][q] = 0;

        const u64* cp[4];
        #pragma unroll
        for (int q = 0; q < 4; q++) cp[q] = (const u64*)(s_c + (cq + 16*q)*130);

        #pragma unroll 2
        for (int e2 = 0; e2 < 64; e2++) {
            u64 zv0 = zp[0][e2], zv1 = zp[1][e2], zv2 = zp[2][e2], zv3 = zp[3][e2];
            u64 cv0 = cp[0][e2], cv1 = cp[1][e2], cv2 = cp[2][e2], cv3 = cp[3][e2];
            dt[0][0] = fma2(zv0, cv0, dt[0][0]); dt[0][1] = fma2(zv0, cv1, dt[0][1]);
            dt[0][2] = fma2(zv0, cv2, dt[0][2]); dt[0][3] = fma2(zv0, cv3, dt[0][3]);
            dt[1][0] = fma2(zv1, cv0, dt[1][0]); dt[1][1] = fma2(zv1, cv1, dt[1][1]);
            dt[1][2] = fma2(zv1, cv2, dt[1][2]); dt[1][3] = fma2(zv1, cv3, dt[1][3]);
            dt[2][0] = fma2(zv2, cv0, dt[2][0]); dt[2][1] = fma2(zv2, cv1, dt[2][1]);
            dt[2][2] = fma2(zv2, cv2, dt[2][2]); dt[2][3] = fma2(zv2, cv3, dt[2][3]);
            dt[3][0] = fma2(zv3, cv0, dt[3][0]); dt[3][1] = fma2(zv3, cv1, dt[3][1]);
            dt[3][2] = fma2(zv3, cv2, dt[3][2]); dt[3][3] = fma2(zv3, cv3, dt[3][3]);
        }

        #pragma unroll
        for (int q = 0; q < 4; q++) {
            float cn = s_cn[cq + 16*q];
            int j = tile*64 + cq + 16*q;
            #pragma unroll
            for (int r = 0; r < 4; r++) {
                float lo, hi; upk2(dt[r][q], lo, hi);
                float d = (s_zn[zq + 16*r] - 2.f*(lo + hi)) + cn;
                if (d < bd[r]) { bd[r] = d; bj[r] = j; }
            }
        }
    }
    #pragma unroll
    for (int r = 0; r < 4; r++) {
        u64 pkv = ((u64)fkey(bd[r]) << 32) | (unsigned)bj[r];
        atomicMin(&s_best[zq + 16*r], pkv);
    }
    __syncthreads();

    if (tid < 64) {
        int j = (int)(s_best[tid] & 0xFFFFFFFFu);
        g_idx[m0 + tid] = j;
        float imv = s_imv[tid];
        if (out_size >= OFF_IDX + MTOT)
            outp[OFF_IDX + m0 + tid] = (imv > 0.f) ? (float)j : -1.f;
        float v = imv;
        #pragma unroll
        for (int off = 16; off; off >>= 1) v += __shfl_down_sync(0xffffffffu, v, off);
        if ((tid & 31) == 0) atomicAdd(&g_acc[3], v);
    }

    // vq loss: (1+BETA) * mean((z - c)^2) * im
    {
        int is = tid >> 2, q = tid & 3;
        int j = (int)(s_best[is] & 0xFFFFFFFFu) & (NE - 1);
        const float* c = cb + (size_t)j*128;
        const float* z = s_z + is*128;
        float s = 0.f;
        for (int e = q*32; e < q*32 + 32; e++) { float d = z[e] - c[e]; s += d*d; }
        s += __shfl_down_sync(0xffffffffu, s, 2, 4);
        s += __shfl_down_sync(0xffffffffu, s, 1, 4);
        if (q == 0) atomicAdd(&g_acc[2], s * ((1.f + BETA)/128.f) * s_imv[is]);
    }
}

// ---------------- fused decoder: 16 inst/block, 4x4 reg tile ------------
#define AP 260
#define WP 260   // sW2 pitch in u64

template<int KHALF, int NOUT>
__device__ __forceinline__ void dec_mm(const float* __restrict__ W,
        const float* __restrict__ sX, u64* __restrict__ sW2,
        u64 (&acc)[16], int tx, int ty, int tid)
{
    #pragma unroll
    for (int z = 0; z < 16; z++) acc[z] = 0;
    for (int kp0 = 0; kp0 < KHALF; kp0 += 4) {
        __syncthreads();
        {
            const int o = tid;
            if (NOUT >= 256 || o < NOUT) {
                const u64* wrow = (const u64*)W + (size_t)o*KHALF + kp0;
                sW2[0*WP + o] = __ldg(wrow + 0);
                sW2[1*WP + o] = __ldg(wrow + 1);
                sW2[2*WP + o] = __ldg(wrow + 2);
                sW2[3*WP + o] = __ldg(wrow + 3);
            } else {
                sW2[0*WP + o] = 0; sW2[1*WP + o] = 0;
                sW2[2*WP + o] = 0; sW2[3*WP + o] = 0;
            }
        }
        __syncthreads();
        u64 a[4][4];
        #pragma unroll
        for (int i = 0; i < 4; i++) {
            const u64* ap = (const u64*)(sX + (size_t)(ty*4 + i)*AP) + kp0;
            a[i][0] = ap[0]; a[i][1] = ap[1]; a[i][2] = ap[2]; a[i][3] = ap[3];
        }
        #pragma unroll
        for (int s = 0; s < 4; s++) {
            u64 w0 = sW2[0*WP + tx + 64*s];
            u64 w1 = sW2[1*WP + tx + 64*s];
            u64 w2 = sW2[2*WP + tx + 64*s];
            u64 w3 = sW2[3*WP + tx + 64*s];
            #pragma unroll
            for (int i = 0; i < 4; i++) {
                u64 v = acc[s*4 + i];
                v = fma2(w0, a[i][0], v);
                v = fma2(w1, a[i][1], v);
                v = fma2(w2, a[i][2], v);
                v = fma2(w3, a[i][3], v);
                acc[s*4 + i] = v;
            }
        }
    }
}

__global__ __launch_bounds__(256)
void k_dec(const float* __restrict__ cb, const float* __restrict__ imask,
           const float* __restrict__ d1w, const float* __restrict__ d1b,
           const float* __restrict__ d2w, const float* __restrict__ d2b,
           const float* __restrict__ d3w, const float* __restrict__ d3b,
           const float* __restrict__ candA, const float* __restrict__ candB,
           float* __restrict__ outp)
{
    __shared__ __align__(16) float sA[16*AP];
    __shared__ __align__(16) float sB[16*AP];
    __shared__ u64 sW2[4*WP];
    __shared__ float s_im[16];
    __shared__ int   s_j[16];

    const int tid = threadIdx.x;
    const int tx  = tid & 63;
    const int ty  = tid >> 6;
    const int m0  = blockIdx.x * 16;

    if (tid < 16) { s_im[tid] = imask[m0 + tid]; s_j[tid] = g_idx[m0 + tid] & (NE - 1); }
    __syncthreads();

    for (int i = tid; i < 16*128; i += 256) {
        int ii = i >> 7, e = i & 127;
        sA[ii*AP + e] = cb[(size_t)s_j[ii]*128 + e] * s_im[ii];
    }
    // (dec_mm's first __syncthreads() orders this against reads)

    u64 acc[16];

    // GEMM1: sB = relu(sA @ d1w^T + d1b), K=128, Nout=256
    dec_mm<64, 256>(d1w, sA, sW2, acc, tx, ty, tid);
    {
        #pragma unroll
        for (int s = 0; s < 4; s++) {
            int o = tx + 64*s;
            float bb = __ldg(d1b + o);
            #pragma unroll
            for (int i = 0; i < 4; i++) {
                float lo, hi; upk2(acc[s*4 + i], lo, hi);
                sB[(ty*4 + i)*AP + o] = fmaxf(lo + hi + bb, 0.f);
            }
        }
    }

    // GEMM2: sA = relu(sB @ d2w^T + d2b), K=256, Nout=256
    dec_mm<128, 256>(d2w, sB, sW2, acc, tx, ty, tid);
    {
        #pragma unroll
        for (int s = 0; s < 4; s++) {
            int o = tx + 64*s;
            float bb = __ldg(d2b + o);
            #pragma unroll
            for (int i = 0; i < 4; i++) {
                float lo, hi; upk2(acc[s*4 + i], lo, hi);
                sA[(ty*4 + i)*AP + o] = fmaxf(lo + hi + bb, 0.f);
            }
        }
    }

    // GEMM3: x_hat = sA @ d3w^T + d3b, K=256, Nout=100, + recon loss
    dec_mm<128, 100>(d3w, sA, sW2, acc, tx, ty, tid);
    {
        const float* xr = candA; const float* tmr = candB;
        if (g_afirst_is_x == 0) { xr = candB; tmr = candA; }

        float rsum = 0.f, wsum = 0.f;
        #pragma unroll
        for (int s = 0; s < 2; s++) {            // o >= 128 never < 100
            int o = tx + 64*s;
            if (o < TT) {
                float bb = __ldg(d3b + o);
                #pragma unroll
                for (int i = 0; i < 4; i++) {
                    int m = m0 + ty*4 + i;
                    float lo, hi; upk2(acc[s*4 + i], lo, hi);
                    float v = lo + hi + bb;
                    outp[(size_t)m*TT + o] = v;
                    float wgt = s_im[ty*4 + i] * tmr[(size_t)m*TT + o];
                    float d = v - xr[(size_t)m*TT + o];
                    rsum += d*d*wgt; wsum += wgt;
                }
            }
        }
        #pragma unroll
        for (int off = 16; off; off >>= 1) {
            rsum += __shfl_down_sync(0xffffffffu, rsum, off);
            wsum += __shfl_down_sync(0xffffffffu, wsum, off);
        }
        if ((tid & 31) == 0) {
            atomicAdd(&g_acc[0], rsum);
            atomicAdd(&g_acc[1], wsum);
        }
    }
}

// ---------------- finalize ----------------
__global__ void k_final(float* __restrict__ outp, int out_size) {
    if (out_size > OFF_VQ) {
        outp[OFF_RECON] = g_acc[0] / fmaxf(g_acc[1], 1.f);
        outp[OFF_VQ]    = g_acc[2] / fmaxf(g_acc[3], 1.f);
    }
}

// ---------------- launch ----------------
extern "C" void kernel_launch(void* const* d_in, const int* in_sizes, int n_in,
                              void* d_out, int out_size)
{
    const float *candA=0,*candB=0,*im=0,*c1w=0,*c1b=0,*c2w=0,*c2b=0;
    const float *latw=0,*latb=0,*cb=0,*d1w=0,*d1b=0,*d2w=0,*d2b=0,*d3w=0,*d3b=0;

    int scale = 1;
    for (int i = 0; i < n_in; i++)
        if (in_sizes[i] == 5120000*4) { scale = 4; break; }

    int c5=0,c64=0,c256=0,c65k=0;
    for (int i = 0; i < n_in; i++) {
        const float* p = (const float*)d_in[i];
        int sz = in_sizes[i] / scale;
        switch (sz) {
            case 5120000: if (c5++ == 0) candA = p; else candB = p; break;
            case 51200:   im   = p; break;
            case 384:     c1w  = p; break;
            case 64:      if (c64++ == 0) c1b = p; else c2b = p; break;
            case 12288:   c2w  = p; break;
            case 8192:    latw = p; break;
            case 128:     latb = p; break;
            case 65536:   if (c65k++ == 0) cb = p; else d2w = p; break;
            case 32768:   d1w  = p; break;
            case 256:     if (c256++ == 0) d1b = p; else d2b = p; break;
            case 25600:   d3w  = p; break;
            case 100:     d3b  = p; break;
            default: break;
        }
    }
    if ((!candA || !candB || !im || !cb || !d1w || !d2w || !d3w) && n_in >= 16) {
        candA = (const float*)d_in[0];  candB = (const float*)d_in[1];
        im    = (const float*)d_in[2];
        c1w   = (const float*)d_in[3];  c1b   = (const float*)d_in[4];
        c2w   = (const float*)d_in[5];  c2b   = (const float*)d_in[6];
        latw  = (const float*)d_in[7];  latb  = (const float*)d_in[8];
        cb    = (const float*)d_in[9];
        d1w   = (const float*)d_in[10]; d1b   = (const float*)d_in[11];
        d2w   = (const float*)d_in[12]; d2b   = (const float*)d_in[13];
        d3w   = (const float*)d_in[14]; d3b   = (const float*)d_in[15];
    }
    if (!candB) candB = candA;

    float* outp = (float*)d_out;

    if (out_size > XH_ELEMS)
        k_zerotail<<<32, 256>>>(outp + XH_ELEMS, out_size - XH_ELEMS);
    k_init<<<2, 256>>>(cb, candA);
    k_encode<<<MTOT/2, 128>>>(candA, candB, im, c1w, c1b, c2w, c2b, latw, latb);
    k_vq<<<MTOT/64, 256>>>(cb, im, outp, out_size);
    k_dec<<<MTOT/16, 256>>>(cb, im, d1w, d1b, d2w, d2b, d3w, d3b, candA, candB, outp);
    k_final<<<1, 1>>>(outp, out_size);
}

// round 7
// speedup vs baseline: 2.6251x; 1.0844x over previous
#include <cuda_runtime.h>
#include <math.h>

// ---------------- problem constants ----------------
#define MB      512
#define NN      100
#define TT      100
#define LL      50
#define HE      64
#define EE      128
#define NE      512
#define HD      256
#define MTOT    (MB*NN)     // 51200
#define BETA    0.25f

#define XH_ELEMS   (MTOT*TT)        // 5,120,000
#define OFF_RECON  (XH_ELEMS)
#define OFF_VQ     (XH_ELEMS+1)
#define OFF_IDX    (XH_ELEMS+2)

typedef unsigned long long u64;

// ---- f32x2 helpers ----
__device__ __forceinline__ u64 pk2(float lo, float hi) {
    u64 r;
    asm("mov.b64 %0, {%1, %2};" : "=l"(r) : "r"(__float_as_uint(lo)), "r"(__float_as_uint(hi)));
    return r;
}
__device__ __forceinline__ void upk2(u64 v, float& lo, float& hi) {
    unsigned a, b;
    asm("mov.b64 {%0, %1}, %2;" : "=r"(a), "=r"(b) : "l"(v));
    lo = __uint_as_float(a); hi = __uint_as_float(b);
}
__device__ __forceinline__ u64 fma2(u64 a, u64 b, u64 c) {
    u64 d;
    asm("fma.rn.f32x2 %0, %1, %2, %3;" : "=l"(d) : "l"(a), "l"(b), "l"(c));
    return d;
}

// ---------------- device scratch ----------------
__device__ float g_z[MTOT*EE];
__device__ int   g_idx[MTOT];
__device__ float g_cnorm[NE];
__device__ float g_acc[4];
__device__ int   g_afirst_is_x;

// ---------------- zero tail ----------------
__global__ void k_zerotail(float* __restrict__ p, int n) {
    int i = blockIdx.x*256 + threadIdx.x;
    int stride = gridDim.x*256;
    for (; i < n; i += stride) p[i] = 0.f;
}

// ---------------- init (accumulators + x/mask flag) ----------------
__global__ void k_init(const float* __restrict__ candA) {
    int j = threadIdx.x;
    if (j < 4) g_acc[j] = 0.f;
    if (j == 4) {
        int all01 = 1;
        if (candA) {
            for (int i = 0; i < 256; i++) {
                float v = candA[i];
                if (v != 0.f && v != 1.f) { all01 = 0; break; }
            }
        } else all01 = 0;
        g_afirst_is_x = all01 ? 0 : 1;
    }
}

// ---------------- init2 (codebook norms) ----------------
__global__ void k_initcn(const float* __restrict__ cb) {
    int j = blockIdx.x*256 + threadIdx.x;
    if (j < NE) {
        const float* c = cb + j*EE;
        float s = 0.f;
        for (int e = 0; e < EE; e++) { float v = c[e]; s += v*v; }
        g_cnorm[j] = s;
    }
}

// ---------------- encoder: 2 inst/block, 256 threads --------------------
// conv2: all weights resident (packed u64 channel-pairs), quarter-l split.
__global__ __launch_bounds__(256)
void k_encode(const float* __restrict__ candA, const float* __restrict__ candB,
              const float* __restrict__ imask,
              const float* __restrict__ w1g, const float* __restrict__ b1g,
              const float* __restrict__ w2g, const float* __restrict__ b2g,
              const float* __restrict__ latw, const float* __restrict__ latb)
{
    __shared__ float s_h1[2*64*54];     // 27.6 KB, halo-padded, zeros outside 1..50
    __shared__ u64   s_w2p[192*32];     // 49.2 KB: [(i*3+k)*32 + o32] = pk2(w[o32], w[o32+32])
    __shared__ float s_h0[2*2*52];
    __shared__ float s_w1[384];
    __shared__ float s_b1[64], s_b2[64];
    __shared__ float s_part[2*64*4];
    __shared__ __align__(16) float s_hbar[2*64];
    __shared__ float s_im[2];

    const int tid = threadIdx.x;
    const int m0  = blockIdx.x * 2;

    for (int i = tid; i < 2*64*54; i += 256) s_h1[i] = 0.f;
    for (int i = tid; i < 2*2*52;  i += 256) s_h0[i] = 0.f;
    for (int i = tid; i < 384;     i += 256) s_w1[i] = w1g[i];
    if (tid < 64)  { s_b1[tid] = b1g[tid]; s_b2[tid] = b2g[tid]; }
    if (tid < 2)   s_im[tid] = imask[m0 + tid];
    // pack conv2 weights: channel pair (o32, o32+32)
    for (int idx = tid; idx < 192*32; idx += 256) {
        int o32 = idx & 31, rk = idx >> 5;
        s_w2p[rk*32 + o32] = pk2(__ldg(w2g + o32*192 + rk), __ldg(w2g + (o32+32)*192 + rk));
    }
    __syncthreads();

    // masked input
    for (int i = tid; i < 2*TT; i += 256) {
        int inst = i / TT, t = i - (i/TT)*TT;
        int m = m0 + inst;
        float v = candA[(size_t)m*TT + t] * candB[(size_t)m*TT + t] * s_im[inst];
        s_h0[(inst*2 + (t & 1))*52 + 1 + (t >> 1)] = v;
    }
    __syncthreads();

    // conv1: thread = (inst, lhalf, o); 25 l each
    {
        const int o = tid & 63, lh = (tid >> 6) & 1, inst = tid >> 7;
        const int lb = lh * 25;
        float w[6];
        #pragma unroll
        for (int q = 0; q < 6; q++) w[q] = s_w1[o*6 + q];
        float bb = s_b1[o];
        const float* p0 = s_h0 + (inst*2 + 0)*52;
        const float* p1 = s_h0 + (inst*2 + 1)*52;
        float* dst = s_h1 + (inst*64 + o)*54;
        #pragma unroll 5
        for (int l = 0; l < 25; l++) {
            int li = lb + l;
            float v = bb + w[0]*p0[li] + w[1]*p0[li+1] + w[2]*p0[li+2]
                         + w[3]*p1[li] + w[4]*p1[li+1] + w[5]*p1[li+2];
            dst[1 + li] = fmaxf(v, 0.f);
        }
    }
    __syncthreads();

    // conv2: thread = (inst, lq, o32); channels (o32, o32+32) packed, 13 l's
    {
        const int o32 = tid & 31, lq = (tid >> 5) & 3, inst = tid >> 7;
        const int lb  = lq * 13;
        const int np  = (lq == 3) ? 11 : 13;

        u64 acc2[13];
        {
            u64 bb2 = pk2(s_b2[o32], s_b2[o32 + 32]);
            #pragma unroll
            for (int x = 0; x < 13; x++) acc2[x] = bb2;
        }
        const float* hbase = s_h1 + inst*64*54 + lb;
        for (int i = 0; i < 64; i++) {
            const float* hrow = hbase + i*54;
            u64 hh[15];
            #pragma unroll
            for (int x = 0; x < 15; x++) { float h = hrow[x]; hh[x] = pk2(h, h); }
            const u64* wb = s_w2p + i*96;
            u64 w0p = wb[o32], w1p = wb[32 + o32], w2p = wb[64 + o32];
            #pragma unroll
            for (int x = 0; x < 13; x++) {
                u64 v = acc2[x];
                v = fma2(w0p, hh[x],   v);
                v = fma2(w1p, hh[x+1], v);
                v = fma2(w2p, hh[x+2], v);
                acc2[x] = v;
            }
        }
        float slo = 0.f, shi = 0.f;
        for (int x = 0; x < np; x++) {
            float lo, hi; upk2(acc2[x], lo, hi);
            slo += fmaxf(lo, 0.f);
            shi += fmaxf(hi, 0.f);
        }
        s_part[(inst*64 + o32)*4 + lq]      = slo;
        s_part[(inst*64 + o32 + 32)*4 + lq] = shi;
    }
    __syncthreads();

    if (tid < 128) {
        const int inst = tid >> 6, o = tid & 63;
        const float* p = s_part + (inst*64 + o)*4;
        s_hbar[inst*64 + o] = (p[0] + p[1] + p[2] + p[3]) * (1.f/50.f);
    }
    __syncthreads();

    // latent: 1 output per thread
    {
        const int e = tid & 127, inst = tid >> 7;
        const u64* hb2 = (const u64*)(s_hbar + inst*64);
        const u64* lw = (const u64*)latw + e*32;
        u64 acc = 0;
        #pragma unroll 8
        for (int kk = 0; kk < 32; kk++) acc = fma2(__ldg(lw + kk), hb2[kk], acc);
        float lo, hi; upk2(acc, lo, hi);
        g_z[(size_t)(m0 + inst)*EE + e] = (lo + hi + __ldg(latb + e)) * s_im[inst];
    }
}

// ---------------- VQ (unchanged from R6: 255us) ----------------
__device__ __forceinline__ unsigned fkey(float f) {
    unsigned u = __float_as_uint(f);
    return (u & 0x80000000u) ? ~u : (u | 0x80000000u);
}

__global__ __launch_bounds__(256)
void k_vq(const float* __restrict__ cb, const float* __restrict__ imask,
          float* __restrict__ outp, int out_size)
{
    __shared__ __align__(16) float s_z[64*128];
    __shared__ __align__(16) float s_c[64*130];
    __shared__ float s_cn[64], s_zn[64], s_imv[64];
    __shared__ u64   s_best[64];

    const int tid = threadIdx.x;
    const int m0  = blockIdx.x * 64;

    for (int i = tid; i < 64*128; i += 256) s_z[i] = g_z[(size_t)m0*128 + i];
    if (tid < 64) { s_best[tid] = 0xFFFFFFFFFFFFFFFFull; s_imv[tid] = imask[m0 + tid]; }
    __syncthreads();
    if (tid < 64) {
        const float* z = s_z + tid*128;
        float s = 0.f;
        for (int e = 0; e < 128; e++) s += z[e]*z[e];
        s_zn[tid] = s;
    }

    const int cq = tid & 15;
    const int zq = tid >> 4;

    float bd[4]; int bj[4];
    #pragma unroll
    for (int r = 0; r < 4; r++) { bd[r] = 3.4e38f; bj[r] = 0; }

    const u64* zp[4];
    #pragma unroll
    for (int r = 0; r < 4; r++) zp[r] = (const u64*)(s_z + (zq + 16*r)*128);

    for (int tile = 0; tile < 8; tile++) {
        __syncthreads();
        for (int i = tid; i < 64*128; i += 256) {
            int row = i >> 7, e = i & 127;
            s_c[row*130 + e] = cb[(size_t)(tile*64 + row)*128 + e];
        }
        if (tid < 64) s_cn[tid] = g_cnorm[tile*64 + tid];
        __syncthreads();

        u64 dt[4][4];
        #pragma unroll
        for (int r = 0; r < 4; r++)
            #pragma unroll
            for (int q = 0; q < 4; q++) dt[r][q] = 0;

        const u64* cp[4];
        #pragma unroll
        for (int q = 0; q < 4; q++) cp[q] = (const u64*)(s_c + (cq + 16*q)*130);

        #pragma unroll 2
        for (int e2 = 0; e2 < 64; e2++) {
            u64 zv0 = zp[0][e2], zv1 = zp[1][e2], zv2 = zp[2][e2], zv3 = zp[3][e2];
            u64 cv0 = cp[0][e2], cv1 = cp[1][e2], cv2 = cp[2][e2], cv3 = cp[3][e2];
            dt[0][0] = fma2(zv0, cv0, dt[0][0]); dt[0][1] = fma2(zv0, cv1, dt[0][1]);
            dt[0][2] = fma2(zv0, cv2, dt[0][2]); dt[0][3] = fma2(zv0, cv3, dt[0][3]);
            dt[1][0] = fma2(zv1, cv0, dt[1][0]); dt[1][1] = fma2(zv1, cv1, dt[1][1]);
            dt[1][2] = fma2(zv1, cv2, dt[1][2]); dt[1][3] = fma2(zv1, cv3, dt[1][3]);
            dt[2][0] = fma2(zv2, cv0, dt[2][0]); dt[2][1] = fma2(zv2, cv1, dt[2][1]);
            dt[2][2] = fma2(zv2, cv2, dt[2][2]); dt[2][3] = fma2(zv2, cv3, dt[2][3]);
            dt[3][0] = fma2(zv3, cv0, dt[3][0]); dt[3][1] = fma2(zv3, cv1, dt[3][1]);
            dt[3][2] = fma2(zv3, cv2, dt[3][2]); dt[3][3] = fma2(zv3, cv3, dt[3][3]);
        }

        #pragma unroll
        for (int q = 0; q < 4; q++) {
            float cn = s_cn[cq + 16*q];
            int j = tile*64 + cq + 16*q;
            #pragma unroll
            for (int r = 0; r < 4; r++) {
                float lo, hi; upk2(dt[r][q], lo, hi);
                float d = (s_zn[zq + 16*r] - 2.f*(lo + hi)) + cn;
                if (d < bd[r]) { bd[r] = d; bj[r] = j; }
            }
        }
    }
    #pragma unroll
    for (int r = 0; r < 4; r++) {
        u64 pkv = ((u64)fkey(bd[r]) << 32) | (unsigned)bj[r];
        atomicMin(&s_best[zq + 16*r], pkv);
    }
    __syncthreads();

    if (tid < 64) {
        int j = (int)(s_best[tid] & 0xFFFFFFFFu);
        g_idx[m0 + tid] = j;
        float imv = s_imv[tid];
        if (out_size >= OFF_IDX + MTOT)
            outp[OFF_IDX + m0 + tid] = (imv > 0.f) ? (float)j : -1.f;
        float v = imv;
        #pragma unroll
        for (int off = 16; off; off >>= 1) v += __shfl_down_sync(0xffffffffu, v, off);
        if ((tid & 31) == 0) atomicAdd(&g_acc[3], v);
    }

    {
        int is = tid >> 2, q = tid & 3;
        int j = (int)(s_best[is] & 0xFFFFFFFFu) & (NE - 1);
        const float* c = cb + (size_t)j*128;
        const float* z = s_z + is*128;
        float s = 0.f;
        for (int e = q*32; e < q*32 + 32; e++) { float d = z[e] - c[e]; s += d*d; }
        s += __shfl_down_sync(0xffffffffu, s, 2, 4);
        s += __shfl_down_sync(0xffffffffu, s, 1, 4);
        if (q == 0) atomicAdd(&g_acc[2], s * ((1.f + BETA)/128.f) * s_imv[is]);
    }
}

// ---------------- decoder: 32 inst/block, 128 threads, 8x8 tile ---------
#define APF 264     // sA/sB pitch (floats), /2 = 132 u64
#define WPU 265     // sW2 pitch (u64)

template<int KHALF, int SGRP>
__device__ __forceinline__ void dec_mm(const float* __restrict__ W, int NOUT,
        const float* sX, u64* sW2, u64 (&acc)[8][8], int tx, int ig, int tid)
{
    #pragma unroll
    for (int i = 0; i < 8; i++)
        #pragma unroll
        for (int s = 0; s < SGRP; s++) acc[i][s] = 0;
    const u64* Wu = (const u64*)W;
    const u64* aX = (const u64*)sX;
    for (int kc = 0; kc < KHALF; kc += 8) {
        __syncthreads();
        for (int idx = tid; idx < 256*8; idx += 128) {
            int row = idx >> 3, r = idx & 7;
            u64 v = 0;
            if (row < NOUT) v = __ldg(Wu + (size_t)row*KHALF + kc + r);
            sW2[r*WPU + row] = v;
        }
        __syncthreads();
        #pragma unroll
        for (int kp = 0; kp < 8; kp++) {
            u64 a8[8], w8[8];
            #pragma unroll
            for (int i = 0; i < 8; i++) a8[i] = aX[(ig*8 + i)*(APF/2) + kc + kp];
            #pragma unroll
            for (int s = 0; s < SGRP; s++) w8[s] = sW2[kp*WPU + tx + 32*s];
            #pragma unroll
            for (int i = 0; i < 8; i++)
                #pragma unroll
                for (int s = 0; s < SGRP; s++)
                    acc[i][s] = fma2(w8[s], a8[i], acc[i][s]);
        }
    }
}

__global__ __launch_bounds__(128, 2)
void k_dec(const float* __restrict__ cb, const float* __restrict__ imask,
           const float* __restrict__ d1w, const float* __restrict__ d1b,
           const float* __restrict__ d2w, const float* __restrict__ d2b,
           const float* __restrict__ d3w, const float* __restrict__ d3b,
           const float* __restrict__ candA, const float* __restrict__ candB,
           float* __restrict__ outp)
{
    __shared__ __align__(16) float sA[32*APF];   // 33.8 KB
    __shared__ __align__(16) float sB[32*APF];   // 33.8 KB
    __shared__ u64 sW2[8*WPU];                   // 17.0 KB
    __shared__ float s_im[32];
    __shared__ int   s_j[32];

    const int tid = threadIdx.x;
    const int tx  = tid & 31;
    const int ig  = tid >> 5;        // 0..3 -> instances ig*8..+7
    const int m0  = blockIdx.x * 32;

    if (tid < 32) { s_im[tid] = imask[m0 + tid]; s_j[tid] = g_idx[m0 + tid] & (NE - 1); }
    __syncthreads();

    // gather zq*im into sA[:, 0:128]
    for (int i = tid; i < 32*128; i += 128) {
        int ii = i >> 7, e = i & 127;
        sA[ii*APF + e] = cb[(size_t)s_j[ii]*128 + e] * s_im[ii];
    }
    // dec_mm's first __syncthreads orders this

    u64 acc[8][8];

    // GEMM1: sB = relu(sA @ d1w^T + d1b), K=128
    dec_mm<64, 8>(d1w, 256, sA, sW2, acc, tx, ig, tid);
    __syncthreads();
    #pragma unroll
    for (int s = 0; s < 8; s++) {
        int o = tx + 32*s;
        float bb = __ldg(d1b + o);
        #pragma unroll
        for (int i = 0; i < 8; i++) {
            float lo, hi; upk2(acc[i][s], lo, hi);
            sB[(ig*8 + i)*APF + o] = fmaxf(lo + hi + bb, 0.f);
        }
    }

    // GEMM2: sA = relu(sB @ d2w^T + d2b), K=256
    dec_mm<128, 8>(d2w, 256, sB, sW2, acc, tx, ig, tid);
    __syncthreads();
    #pragma unroll
    for (int s = 0; s < 8; s++) {
        int o = tx + 32*s;
        float bb = __ldg(d2b + o);
        #pragma unroll
        for (int i = 0; i < 8; i++) {
            float lo, hi; upk2(acc[i][s], lo, hi);
            sA[(ig*8 + i)*APF + o] = fmaxf(lo + hi + bb, 0.f);
        }
    }

    // GEMM3: x_hat = sA @ d3w^T + d3b (Nout=100) + recon loss
    dec_mm<128, 4>(d3w, 100, sA, sW2, acc, tx, ig, tid);
    {
        const float* xr = candA; const float* tmr = candB;
        if (g_afirst_is_x == 0) { xr = candB; tmr = candA; }

        float rsum = 0.f, wsum = 0.f;
        #pragma unroll
        for (int s = 0; s < 4; s++) {
            int o = tx + 32*s;
            if (o < TT) {
                float bb = __ldg(d3b + o);
                #pragma unroll
                for (int i = 0; i < 8; i++) {
                    int m = m0 + ig*8 + i;
                    float lo, hi; upk2(acc[i][s], lo, hi);
                    float v = lo + hi + bb;
                    outp[(size_t)m*TT + o] = v;
                    float wgt = s_im[ig*8 + i] * tmr[(size_t)m*TT + o];
                    float d = v - xr[(size_t)m*TT + o];
                    rsum += d*d*wgt; wsum += wgt;
                }
            }
        }
        #pragma unroll
        for (int off = 16; off; off >>= 1) {
            rsum += __shfl_down_sync(0xffffffffu, rsum, off);
            wsum += __shfl_down_sync(0xffffffffu, wsum, off);
        }
        if ((tid & 31) == 0) {
            atomicAdd(&g_acc[0], rsum);
            atomicAdd(&g_acc[1], wsum);
        }
    }
}

// ---------------- finalize ----------------
__global__ void k_final(float* __restrict__ outp, int out_size) {
    if (out_size > OFF_VQ) {
        outp[OFF_RECON] = g_acc[0] / fmaxf(g_acc[1], 1.f);
        outp[OFF_VQ]    = g_acc[2] / fmaxf(g_acc[3], 1.f);
    }
}

// ---------------- launch ----------------
extern "C" void kernel_launch(void* const* d_in, const int* in_sizes, int n_in,
                              void* d_out, int out_size)
{
    const float *candA=0,*candB=0,*im=0,*c1w=0,*c1b=0,*c2w=0,*c2b=0;
    const float *latw=0,*latb=0,*cb=0,*d1w=0,*d1b=0,*d2w=0,*d2b=0,*d3w=0,*d3b=0;

    int scale = 1;
    for (int i = 0; i < n_in; i++)
        if (in_sizes[i] == 5120000*4) { scale = 4; break; }

    int c5=0,c64=0,c256=0,c65k=0;
    for (int i = 0; i < n_in; i++) {
        const float* p = (const float*)d_in[i];
        int sz = in_sizes[i] / scale;
        switch (sz) {
            case 5120000: if (c5++ == 0) candA = p; else candB = p; break;
            case 51200:   im   = p; break;
            case 384:     c1w  = p; break;
            case 64:      if (c64++ == 0) c1b = p; else c2b = p; break;
            case 12288:   c2w  = p; break;
            case 8192:    latw = p; break;
            case 128:     latb = p; break;
            case 65536:   if (c65k++ == 0) cb = p; else d2w = p; break;
            case 32768:   d1w  = p; break;
            case 256:     if (c256++ == 0) d1b = p; else d2b = p; break;
            case 25600:   d3w  = p; break;
            case 100:     d3b  = p; break;
            default: break;
        }
    }
    if ((!candA || !candB || !im || !cb || !d1w || !d2w || !d3w) && n_in >= 16) {
        candA = (const float*)d_in[0];  candB = (const float*)d_in[1];
        im    = (const float*)d_in[2];
        c1w   = (const float*)d_in[3];  c1b   = (const float*)d_in[4];
        c2w   = (const float*)d_in[5];  c2b   = (const float*)d_in[6];
        latw  = (const float*)d_in[7];  latb  = (const float*)d_in[8];
        cb    = (const float*)d_in[9];
        d1w   = (const float*)d_in[10]; d1b   = (const float*)d_in[11];
        d2w   = (const float*)d_in[12]; d2b   = (const float*)d_in[13];
        d3w   = (const float*)d_in[14]; d3b   = (const float*)d_in[15];
    }
    if (!candB) candB = candA;

    float* outp = (float*)d_out;

    k_zerotail<<<32, 256>>>(outp + XH_ELEMS, out_size > XH_ELEMS ? out_size - XH_ELEMS : 0);  // launch 1
    k_init<<<1, 32>>>(candA);                                                                  // launch 2
    k_initcn<<<2, 256>>>(cb);                                                                  // launch 3
    k_encode<<<MTOT/2, 256>>>(candA, candB, im, c1w, c1b, c2w, c2b, latw, latb);               // launch 4 (profiled)
    k_vq<<<MTOT/64, 256>>>(cb, im, outp, out_size);                                            // launch 5
    k_dec<<<MTOT/32, 128>>>(cb, im, d1w, d1b, d2w, d2b, d3w, d3b, candA, candB, outp);         // launch 6
    k_final<<<1, 1>>>(outp, out_size);                                                         // launch 7
}